// round 1
// baseline (speedup 1.0000x reference)
#include <cuda_runtime.h>
#include <math.h>

#define BATCH 16
#define DIMC 256
#define HH 56
#define WW 56
#define HEADS 8
#define DH 32
#define HW 3136      // 56*56
#define H28 28
#define S28 784      // 28*28
#define HP 14
#define SP 196       // 14*14

// ---------------- scratch (static device globals; no allocation) ----------------
__device__ float g_q    [BATCH * DIMC * HW];        // q_local  (b, c, hw)
__device__ float g_p28a [BATCH * DIMC * S28];       // after dw s2 + bn0
__device__ float g_p28b [BATCH * DIMC * S28];       // after pl0 1x1
__device__ float g_p14  [BATCH * DIMC * SP];        // after dw s2 + bn1
__device__ float g_kv   [BATCH * 2 * DIMC * SP];    // kv proj (b, 512, 196)
__device__ float g_attn [BATCH * HEADS * HW * SP];  // 315MB attention matrix
__device__ float g_gf   [BATCH * DIMC * HW];        // global feature (b, c, hw)
__device__ float g_mixin[BATCH * DIMC * HW];        // gated product, input to mix conv

// ---------------- generic tiled GEMM ----------------
// C[o,i][m][n] = alpha * sum_k A[m,k] * B[k,n] + bias[m]
// A element at A + o*a_s1 + i*a_s2 + m*a_rs + k*a_cs
// B element at B + o*b_s1 + i*b_s2 + k*b_rs + n*b_cs
// C row-major (m*N + n) at C + o*c_s1 + i*c_s2
#define BM 64
#define BN 64
#define BKK 16

__global__ __launch_bounds__(256) void gemm_k(
    const float* __restrict__ Abase, const float* __restrict__ Bbase,
    const float* __restrict__ bias, float* __restrict__ Cbase,
    int M, int N, int Kd, int bdiv,
    long a_s1, long a_s2, long b_s1, long b_s2, long c_s1, long c_s2,
    int a_rs, int a_cs, int b_rs, int b_cs, float alpha)
{
    int bz = blockIdx.z;
    int o = bz / bdiv, ii = bz % bdiv;
    const float* A = Abase + o * a_s1 + ii * a_s2;
    const float* B = Bbase + o * b_s1 + ii * b_s2;
    float* C = Cbase + o * c_s1 + ii * c_s2;

    __shared__ float As[BKK][BM + 1];
    __shared__ float Bs[BKK][BN + 1];

    int m0 = blockIdx.y * BM;
    int n0 = blockIdx.x * BN;
    int t = threadIdx.x;
    int tx = t & 15;        // n direction (16)
    int ty = t >> 4;        // m direction (16)

    float acc[4][4];
#pragma unroll
    for (int a = 0; a < 4; a++)
#pragma unroll
        for (int b = 0; b < 4; b++) acc[a][b] = 0.f;

    for (int k0 = 0; k0 < Kd; k0 += BKK) {
        // ---- load A tile (pick loop order so unit-stride dim is fastest) ----
        if (a_cs == 1) {
#pragma unroll
            for (int r = 0; r < 4; r++) {
                int idx = t + r * 256;
                int kk = idx & (BKK - 1);
                int mm = idx / BKK;
                int m = m0 + mm, k = k0 + kk;
                As[kk][mm] = (m < M && k < Kd) ? A[(long)m * a_rs + k] : 0.f;
            }
        } else {
#pragma unroll
            for (int r = 0; r < 4; r++) {
                int idx = t + r * 256;
                int mm = idx & (BM - 1);
                int kk = idx / BM;
                int m = m0 + mm, k = k0 + kk;
                As[kk][mm] = (m < M && k < Kd) ? A[(long)m * a_rs + (long)k * a_cs] : 0.f;
            }
        }
        // ---- load B tile ----
        if (b_cs == 1) {
#pragma unroll
            for (int r = 0; r < 4; r++) {
                int idx = t + r * 256;
                int nn = idx & (BN - 1);
                int kk = idx / BN;
                int k = k0 + kk, n = n0 + nn;
                Bs[kk][nn] = (k < Kd && n < N) ? B[(long)k * b_rs + n] : 0.f;
            }
        } else {
#pragma unroll
            for (int r = 0; r < 4; r++) {
                int idx = t + r * 256;
                int kk = idx & (BKK - 1);
                int nn = idx / BKK;
                int k = k0 + kk, n = n0 + nn;
                Bs[kk][nn] = (k < Kd && n < N) ? B[(long)k * b_rs + (long)n * b_cs] : 0.f;
            }
        }
        __syncthreads();

#pragma unroll
        for (int kk = 0; kk < BKK; kk++) {
            float av[4], bv[4];
#pragma unroll
            for (int a = 0; a < 4; a++) av[a] = As[kk][ty * 4 + a];
#pragma unroll
            for (int b = 0; b < 4; b++) bv[b] = Bs[kk][tx * 4 + b];
#pragma unroll
            for (int a = 0; a < 4; a++)
#pragma unroll
                for (int b = 0; b < 4; b++) acc[a][b] += av[a] * bv[b];
        }
        __syncthreads();
    }

#pragma unroll
    for (int a = 0; a < 4; a++) {
        int m = m0 + ty * 4 + a;
        if (m >= M) continue;
        float bval = bias ? bias[m] : 0.f;
#pragma unroll
        for (int b = 0; b < 4; b++) {
            int n = n0 + tx * 4 + b;
            if (n >= N) continue;
            C[(long)m * N + n] = acc[a][b] * alpha + bval;
        }
    }
}

// ---------------- depthwise 5x5 conv (+ optional BN) ----------------
__global__ void dwconv_bn_k(
    const float* __restrict__ x, const float* __restrict__ w, const float* __restrict__ cb,
    const float* __restrict__ bng, const float* __restrict__ bnb,
    const float* __restrict__ bnm, const float* __restrict__ bnv,
    float* __restrict__ y,
    int Hin, int Win, int Hout, int Wout, int stride, int useBn)
{
    long idx = (long)blockIdx.x * blockDim.x + threadIdx.x;
    long total = (long)BATCH * DIMC * Hout * Wout;
    if (idx >= total) return;
    int ow = idx % Wout;
    long r = idx / Wout;
    int oh = r % Hout; r /= Hout;
    int c = r % DIMC;
    long bc = idx / ((long)Hout * Wout);   // b*DIMC + c
    const float* xp = x + bc * Hin * Win;
    const float* wp = w + c * 25;
    float acc = cb[c];
    int ih0 = oh * stride - 2, iw0 = ow * stride - 2;
#pragma unroll
    for (int kh = 0; kh < 5; kh++) {
        int ih = ih0 + kh;
        if (ih < 0 || ih >= Hin) continue;
#pragma unroll
        for (int kw = 0; kw < 5; kw++) {
            int iw = iw0 + kw;
            if (iw < 0 || iw >= Win) continue;
            acc += xp[ih * Win + iw] * wp[kh * 5 + kw];
        }
    }
    if (useBn) {
        float sc = bng[c] * rsqrtf(bnv[c] + 1e-5f);
        acc = (acc - bnm[c]) * sc + bnb[c];
    }
    y[idx] = acc;
}

// ---------------- row softmax over 196 keys (one warp per row) ----------------
__global__ void softmax196_k(float* __restrict__ attn, long rows)
{
    long warp = ((long)blockIdx.x * blockDim.x + threadIdx.x) >> 5;
    int ln = threadIdx.x & 31;
    if (warp >= rows) return;
    float* row = attn + warp * SP;
    float v[7];
    float mx = -1e30f;
#pragma unroll
    for (int i = 0; i < 7; i++) {
        int idx = ln + 32 * i;
        v[i] = (idx < SP) ? row[idx] : -1e30f;
        mx = fmaxf(mx, v[i]);
    }
#pragma unroll
    for (int off = 16; off; off >>= 1) mx = fmaxf(mx, __shfl_xor_sync(0xffffffffu, mx, off));
    float s = 0.f;
#pragma unroll
    for (int i = 0; i < 7; i++) {
        int idx = ln + 32 * i;
        v[i] = (idx < SP) ? expf(v[i] - mx) : 0.f;
        s += v[i];
    }
#pragma unroll
    for (int off = 16; off; off >>= 1) s += __shfl_xor_sync(0xffffffffu, s, off);
    float inv = 1.f / s;
#pragma unroll
    for (int i = 0; i < 7; i++) {
        int idx = ln + 32 * i;
        if (idx < SP) row[idx] = v[i] * inv;
    }
}

// ---------------- fused local mixer: dwconv5x5(q_local) + silu + global gating ----------------
__global__ void gate_k(
    const float* __restrict__ qloc, const float* __restrict__ gf,
    const float* __restrict__ lw, const float* __restrict__ lb,
    float* __restrict__ out)
{
    long idx = (long)blockIdx.x * blockDim.x + threadIdx.x;
    if (idx >= (long)BATCH * DIMC * HW) return;
    int s = idx % HW;
    int c = (idx / HW) % DIMC;
    int ow = s % WW, oh = s / WW;
    const float* xp = qloc + (idx / HW) * HW;
    const float* wp = lw + c * 25;
    float acc = lb[c];
#pragma unroll
    for (int kh = 0; kh < 5; kh++) {
        int ih = oh - 2 + kh;
        if (ih < 0 || ih >= HH) continue;
#pragma unroll
        for (int kw = 0; kw < 5; kw++) {
            int iw = ow - 2 + kw;
            if (iw < 0 || iw >= WW) continue;
            acc += xp[ih * WW + iw] * wp[kh * 5 + kw];
        }
    }
    float l = acc;
    float lf = l * (1.f / (1.f + expf(-l)));       // silu
    float g = gf[idx];
    float gated = lf * (1.f / (1.f + expf(-g)));   // local2global gate
    out[idx] = gated * g;                           // multiplied by global feat (mix input)
}

// ---------------- host side ----------------
static inline int cdiv(int a, int b) { return (a + b - 1) / b; }

extern "C" void kernel_launch(void* const* d_in, const int* in_sizes, int n_in,
                              void* d_out, int out_size)
{
    const float* x     = (const float*)d_in[0];
    const float* q_w   = (const float*)d_in[1];
    const float* q_b   = (const float*)d_in[2];
    const float* kv_w  = (const float*)d_in[3];
    const float* kv_b  = (const float*)d_in[4];
    const float* p0_w  = (const float*)d_in[5];
    const float* p0_b  = (const float*)d_in[6];
    const float* bn0_g = (const float*)d_in[7];
    const float* bn0_b = (const float*)d_in[8];
    const float* bn0_m = (const float*)d_in[9];
    const float* bn0_v = (const float*)d_in[10];
    const float* pl0_w = (const float*)d_in[11];
    const float* pl0_b = (const float*)d_in[12];
    const float* p1_w  = (const float*)d_in[13];
    const float* p1_b  = (const float*)d_in[14];
    const float* bn1_g = (const float*)d_in[15];
    const float* bn1_b = (const float*)d_in[16];
    const float* bn1_m = (const float*)d_in[17];
    const float* bn1_v = (const float*)d_in[18];
    const float* loc_w = (const float*)d_in[19];
    const float* loc_b = (const float*)d_in[20];
    const float* mix_w = (const float*)d_in[21];
    const float* mix_b = (const float*)d_in[22];
    float* out = (float*)d_out;

    float *q, *p28a, *p28b, *p14, *kv, *attn, *gf, *mixin;
    cudaGetSymbolAddress((void**)&q,     g_q);
    cudaGetSymbolAddress((void**)&p28a,  g_p28a);
    cudaGetSymbolAddress((void**)&p28b,  g_p28b);
    cudaGetSymbolAddress((void**)&p14,   g_p14);
    cudaGetSymbolAddress((void**)&kv,    g_kv);
    cudaGetSymbolAddress((void**)&attn,  g_attn);
    cudaGetSymbolAddress((void**)&gf,    g_gf);
    cudaGetSymbolAddress((void**)&mixin, g_mixin);

    dim3 tb(256);
    const float scalor = 0.17677669529663687f;  // 32^-0.5

    // 1) q_local = 1x1 conv (W[256,256] @ x[b][256,3136])
    gemm_k<<<dim3(cdiv(HW, BN), cdiv(DIMC, BM), BATCH), tb>>>(
        q_w, x, q_b, q,
        DIMC, HW, DIMC, 1,
        0, 0, (long)DIMC * HW, 0, (long)DIMC * HW, 0,
        DIMC, 1, HW, 1, 1.f);

    // 2) p0: dwconv 5x5 s2 + BN0  (56->28)
    dwconv_bn_k<<<cdiv(BATCH * DIMC * S28, 256), tb>>>(
        x, p0_w, p0_b, bn0_g, bn0_b, bn0_m, bn0_v, p28a,
        HH, WW, H28, H28, 2, 1);

    // 3) pl0: 1x1 conv on 28x28
    gemm_k<<<dim3(cdiv(S28, BN), cdiv(DIMC, BM), BATCH), tb>>>(
        pl0_w, p28a, pl0_b, p28b,
        DIMC, S28, DIMC, 1,
        0, 0, (long)DIMC * S28, 0, (long)DIMC * S28, 0,
        DIMC, 1, S28, 1, 1.f);

    // 4) p1: dwconv 5x5 s2 + BN1  (28->14)
    dwconv_bn_k<<<cdiv(BATCH * DIMC * SP, 256), tb>>>(
        p28b, p1_w, p1_b, bn1_g, bn1_b, bn1_m, bn1_v, p14,
        H28, H28, HP, HP, 2, 1);

    // 5) kv = 1x1 conv (W[512,256] @ p[b][256,196])
    gemm_k<<<dim3(cdiv(SP, BN), cdiv(2 * DIMC, BM), BATCH), tb>>>(
        kv_w, p14, kv_b, kv,
        2 * DIMC, SP, DIMC, 1,
        0, 0, (long)DIMC * SP, 0, (long)2 * DIMC * SP, 0,
        DIMC, 1, SP, 1, 1.f);

    // 6) S = scalor * Q @ K^T   per (b,h): M=3136(s) N=196(key) K=32(d)
    //    A = q: elem = q[b*256*3136 + (h*32+d)*3136 + s]  -> a_rs(m=s)=1, a_cs(k=d)=3136
    //    B = K part of kv: kv[b*512*196 + (h*32+d)*196 + key] -> b_rs=196, b_cs=1
    gemm_k<<<dim3(cdiv(SP, BN), cdiv(HW, BM), BATCH * HEADS), tb>>>(
        q, kv, nullptr, attn,
        HW, SP, DH, HEADS,
        (long)DIMC * HW, (long)DH * HW,
        (long)2 * DIMC * SP, (long)DH * SP,
        (long)HEADS * HW * SP, (long)HW * SP,
        1, HW, SP, 1, scalor);

    // 7) softmax over 196 keys, one warp per row
    {
        long rows = (long)BATCH * HEADS * HW;
        long blocks = (rows * 32 + 255) / 256;
        softmax196_k<<<(int)blocks, tb>>>(attn, rows);
    }

    // 8) GF = V^T-ish: per (b,h): C[d][s] = sum_key V[d][key] * P[s][key]
    //    A = V: kv + 256*196 offset; A[m=d][k=key] -> a_rs=196, a_cs=1
    //    B = P: attn; B[k=key][n=s] = P[s*196+key] -> b_rs=1, b_cs=196
    gemm_k<<<dim3(cdiv(HW, BN), cdiv(DH, BM), BATCH * HEADS), tb>>>(
        kv + (long)DIMC * SP, attn, nullptr, gf,
        DH, HW, SP, HEADS,
        (long)2 * DIMC * SP, (long)DH * SP,
        (long)HEADS * HW * SP, (long)HW * SP,
        (long)DIMC * HW, (long)DH * HW,
        SP, 1, 1, SP, 1.f);

    // 9) local mixer + gating -> mix input
    gate_k<<<cdiv(BATCH * DIMC * HW, 256), tb>>>(q, gf, loc_w, loc_b, mixin);

    // 10) mix 1x1 conv -> d_out
    gemm_k<<<dim3(cdiv(HW, BN), cdiv(DIMC, BM), BATCH), tb>>>(
        mix_w, mixin, mix_b, out,
        DIMC, HW, DIMC, 1,
        0, 0, (long)DIMC * HW, 0, (long)DIMC * HW, 0,
        DIMC, 1, HW, 1, 1.f);
}

// round 3
// speedup vs baseline: 1.5410x; 1.5410x over previous
#include <cuda_runtime.h>
#include <math.h>

#define BATCH 16
#define DIMC 256
#define HH 56
#define WW 56
#define HEADS 8
#define DH 32
#define HW 3136      // 56*56
#define H28 28
#define S28 784      // 28*28
#define HP 14
#define SP 196       // 14*14
#define SCAL 0.17677669529663687f

// ---------------- scratch ----------------
__device__ float g_q    [BATCH * DIMC * HW];
__device__ float g_p28a [BATCH * DIMC * S28];
__device__ float g_p28b [BATCH * DIMC * S28];
__device__ float g_p14  [BATCH * DIMC * SP];
__device__ float g_kv   [BATCH * 2 * DIMC * SP];
__device__ float g_gf   [BATCH * DIMC * HW];
__device__ float g_mixin[BATCH * DIMC * HW];

// ---------------- 1x1 conv GEMM: Y[b][m][n] = sum_k W[m][k] X[b][k][n] + bias[m] ----------------
#define GM 128
#define GN 128
#define GK 16

__global__ __launch_bounds__(256) void conv1x1_k(
    const float* __restrict__ W, const float* __restrict__ X,
    const float* __restrict__ bias, float* __restrict__ Y,
    int M, int N, int K)
{
    __shared__ float As[GK][GM + 1];
    __shared__ float Bs[GK][GN];

    int bz = blockIdx.z;
    const float* Xb = X + (long)bz * K * N;
    float* Yb = Y + (long)bz * M * N;
    int m0 = blockIdx.y * GM;
    int n0 = blockIdx.x * GN;
    int t = threadIdx.x;

    int am = t >> 1;             // 0..127
    int ak = (t & 1) * 8;        // 0 or 8
    int bk = t >> 4;             // 0..15
    int bn = (t & 15) * 8;       // 0..120
    int ty = t >> 4, tx = t & 15;

    bool fullN = (n0 + GN <= N);

    float acc[8][8];
#pragma unroll
    for (int i = 0; i < 8; i++)
#pragma unroll
        for (int j = 0; j < 8; j++) acc[i][j] = 0.f;

    for (int k0 = 0; k0 < K; k0 += GK) {
        // A tile: W[(m0+am)][k0+ak..+7]
        {
            const float* wp = W + (long)(m0 + am) * K + k0 + ak;
            float4 a0 = *(const float4*)wp;
            float4 a1 = *(const float4*)(wp + 4);
            As[ak + 0][am] = a0.x; As[ak + 1][am] = a0.y;
            As[ak + 2][am] = a0.z; As[ak + 3][am] = a0.w;
            As[ak + 4][am] = a1.x; As[ak + 5][am] = a1.y;
            As[ak + 6][am] = a1.z; As[ak + 7][am] = a1.w;
        }
        // B tile: X[(k0+bk)][n0+bn..+7]
        {
            const float* xp = Xb + (long)(k0 + bk) * N + n0 + bn;
            if (fullN) {
                *(float4*)&Bs[bk][bn]     = *(const float4*)xp;
                *(float4*)&Bs[bk][bn + 4] = *(const float4*)(xp + 4);
            } else {
#pragma unroll
                for (int u = 0; u < 8; u++)
                    Bs[bk][bn + u] = (n0 + bn + u < N) ? xp[u] : 0.f;
            }
        }
        __syncthreads();

#pragma unroll
        for (int kk = 0; kk < GK; kk++) {
            float av[8], bv[8];
#pragma unroll
            for (int i = 0; i < 8; i++) av[i] = As[kk][ty * 8 + i];
            float4 b0 = *(const float4*)&Bs[kk][tx * 8];
            float4 b1 = *(const float4*)&Bs[kk][tx * 8 + 4];
            bv[0] = b0.x; bv[1] = b0.y; bv[2] = b0.z; bv[3] = b0.w;
            bv[4] = b1.x; bv[5] = b1.y; bv[6] = b1.z; bv[7] = b1.w;
#pragma unroll
            for (int i = 0; i < 8; i++)
#pragma unroll
                for (int j = 0; j < 8; j++) acc[i][j] += av[i] * bv[j];
        }
        __syncthreads();
    }

#pragma unroll
    for (int i = 0; i < 8; i++) {
        int m = m0 + ty * 8 + i;
        float bval = bias[m];
        float* yp = Yb + (long)m * N;
#pragma unroll
        for (int j = 0; j < 8; j++) {
            int n = n0 + tx * 8 + j;
            if (n < N) yp[n] = acc[i][j] + bval;
        }
    }
}

// ---------------- fused flash attention over pooled KV ----------------
#define QT 128
#define QS_STRIDE 132
#define KS_STRIDE 204
#define VS_STRIDE 205
#define PS_STRIDE 197
#define ATTN_SMEM_BYTES ((32 * QS_STRIDE + 32 * KS_STRIDE + 32 * VS_STRIDE + QT * PS_STRIDE) * 4)

__global__ __launch_bounds__(256) void attn_k(
    const float* __restrict__ q, const float* __restrict__ kv, float* __restrict__ gf)
{
    extern __shared__ float sm[];
    float* Qs  = sm;                          // [32][QS_STRIDE]  Qs[d][s] (pre-scaled)
    float* Kst = Qs + 32 * QS_STRIDE;         // [32][KS_STRIDE]  Kst[d][key]
    float* Vst = Kst + 32 * KS_STRIDE;        // [32][VS_STRIDE]  Vst[d][key]
    float* Ps  = Vst + 32 * VS_STRIDE;        // [QT][PS_STRIDE]  S / P

    int bh = blockIdx.y;
    int b = bh >> 3, h = bh & 7;
    int s0 = blockIdx.x * QT;
    const float* qb = q  + ((long)b * DIMC + h * DH) * HW;
    const float* kb = kv + ((long)b * 2 * DIMC + h * DH) * SP;
    const float* vb = kb + (long)DIMC * SP;
    float* gfb = gf + ((long)b * DIMC + h * DH) * HW;

    int t = threadIdx.x;

    // ---- load Q (scaled), K, V ----
    {
        int d = t >> 3;
        int ss = (t & 7) * 16;
#pragma unroll
        for (int u = 0; u < 16; u++) {
            int s = s0 + ss + u;
            Qs[d * QS_STRIDE + ss + u] = (s < HW) ? qb[(long)d * HW + s] * SCAL : 0.f;
        }
        int kbase = (t & 7) * 25;
#pragma unroll
        for (int u = 0; u < 25; u++) {
            int key = kbase + u;
            if (key < SP) {
                Kst[d * KS_STRIDE + key] = kb[(long)d * SP + key];
                Vst[d * VS_STRIDE + key] = vb[(long)d * SP + key];
            }
        }
    }
    __syncthreads();

    // ---- S = Qs^T Kst : M=128(s) x N=196(key), K=32(d) ----
    {
        int ty = t >> 4, tx = t & 15;
#pragma unroll
        for (int kc = 0; kc < 4; kc++) {
            int kn0 = kc * 64;
            if (kc == 3 && tx != 0) break;
            float acc[8][4];
#pragma unroll
            for (int i = 0; i < 8; i++)
#pragma unroll
                for (int j = 0; j < 4; j++) acc[i][j] = 0.f;
#pragma unroll
            for (int kk = 0; kk < 32; kk++) {
                float4 a0 = *(const float4*)&Qs[kk * QS_STRIDE + ty * 8];
                float4 a1 = *(const float4*)&Qs[kk * QS_STRIDE + ty * 8 + 4];
                float4 bb = *(const float4*)&Kst[kk * KS_STRIDE + kn0 + tx * 4];
                float av[8] = {a0.x, a0.y, a0.z, a0.w, a1.x, a1.y, a1.z, a1.w};
                float bv[4] = {bb.x, bb.y, bb.z, bb.w};
#pragma unroll
                for (int i = 0; i < 8; i++)
#pragma unroll
                    for (int j = 0; j < 4; j++) acc[i][j] += av[i] * bv[j];
            }
#pragma unroll
            for (int i = 0; i < 8; i++)
#pragma unroll
                for (int j = 0; j < 4; j++)
                    Ps[(ty * 8 + i) * PS_STRIDE + kn0 + tx * 4 + j] = acc[i][j];
        }
    }
    __syncthreads();

    // ---- softmax rows (196 keys); warp w handles rows w*16..w*16+15 ----
    {
        int w = t >> 5, ln = t & 31;
        for (int rr = 0; rr < 16; rr++) {
            float* row = Ps + (w * 16 + rr) * PS_STRIDE;
            float v[7];
            float mx = -1e30f;
#pragma unroll
            for (int u = 0; u < 7; u++) {
                int idx = ln + 32 * u;
                v[u] = (idx < SP) ? row[idx] : -1e30f;
                mx = fmaxf(mx, v[u]);
            }
#pragma unroll
            for (int off = 16; off; off >>= 1) mx = fmaxf(mx, __shfl_xor_sync(0xffffffffu, mx, off));
            float s = 0.f;
#pragma unroll
            for (int u = 0; u < 7; u++) {
                int idx = ln + 32 * u;
                v[u] = (idx < SP) ? __expf(v[u] - mx) : 0.f;
                s += v[u];
            }
#pragma unroll
            for (int off = 16; off; off >>= 1) s += __shfl_xor_sync(0xffffffffu, s, off);
            float inv = 1.f / s;
#pragma unroll
            for (int u = 0; u < 7; u++) {
                int idx = ln + 32 * u;
                if (idx < SP) row[idx] = v[u] * inv;
            }
        }
    }
    __syncthreads();

    // ---- O = P V^T : M=128(s) x N=32(d), K=196 ----
    {
        int ty = t >> 3;      // 0..31 -> 4 s-rows
        int tx = t & 7;       // 0..7  -> 4 d-cols
        float o[4][4];
#pragma unroll
        for (int i = 0; i < 4; i++)
#pragma unroll
            for (int j = 0; j < 4; j++) o[i][j] = 0.f;
#pragma unroll 4
        for (int key = 0; key < SP; key++) {
            float av[4], bv[4];
#pragma unroll
            for (int i = 0; i < 4; i++) av[i] = Ps[(ty * 4 + i) * PS_STRIDE + key];
#pragma unroll
            for (int j = 0; j < 4; j++) bv[j] = Vst[(tx * 4 + j) * VS_STRIDE + key];
#pragma unroll
            for (int i = 0; i < 4; i++)
#pragma unroll
                for (int j = 0; j < 4; j++) o[i][j] += av[i] * bv[j];
        }
#pragma unroll
        for (int i = 0; i < 4; i++) {
            int s = s0 + ty * 4 + i;
            if (s < HW) {
#pragma unroll
                for (int j = 0; j < 4; j++)
                    gfb[(long)(tx * 4 + j) * HW + s] = o[i][j];
            }
        }
    }
}

// ---------------- depthwise 5x5 conv (+ optional BN) ----------------
__global__ void dwconv_bn_k(
    const float* __restrict__ x, const float* __restrict__ w, const float* __restrict__ cb,
    const float* __restrict__ bng, const float* __restrict__ bnb,
    const float* __restrict__ bnm, const float* __restrict__ bnv,
    float* __restrict__ y,
    int Hin, int Win, int Hout, int Wout, int stride, int useBn)
{
    long idx = (long)blockIdx.x * blockDim.x + threadIdx.x;
    long total = (long)BATCH * DIMC * Hout * Wout;
    if (idx >= total) return;
    int ow = idx % Wout;
    long r = idx / Wout;
    int oh = r % Hout; r /= Hout;
    int c = r % DIMC;
    long bc = idx / ((long)Hout * Wout);
    const float* xp = x + bc * Hin * Win;
    const float* wp = w + c * 25;
    float acc = cb[c];
    int ih0 = oh * stride - 2, iw0 = ow * stride - 2;
#pragma unroll
    for (int kh = 0; kh < 5; kh++) {
        int ih = ih0 + kh;
        if (ih < 0 || ih >= Hin) continue;
#pragma unroll
        for (int kw = 0; kw < 5; kw++) {
            int iw = iw0 + kw;
            if (iw < 0 || iw >= Win) continue;
            acc += xp[ih * Win + iw] * wp[kh * 5 + kw];
        }
    }
    if (useBn) {
        float sc = bng[c] * rsqrtf(bnv[c] + 1e-5f);
        acc = (acc - bnm[c]) * sc + bnb[c];
    }
    y[idx] = acc;
}

// ---------------- fused local mixer + gating ----------------
__global__ void gate_k(
    const float* __restrict__ qloc, const float* __restrict__ gf,
    const float* __restrict__ lw, const float* __restrict__ lb,
    float* __restrict__ out)
{
    long idx = (long)blockIdx.x * blockDim.x + threadIdx.x;
    if (idx >= (long)BATCH * DIMC * HW) return;
    int s = idx % HW;
    int c = (idx / HW) % DIMC;
    int ow = s % WW, oh = s / WW;
    const float* xp = qloc + (idx / HW) * HW;
    const float* wp = lw + c * 25;
    float acc = lb[c];
#pragma unroll
    for (int kh = 0; kh < 5; kh++) {
        int ih = oh - 2 + kh;
        if (ih < 0 || ih >= HH) continue;
#pragma unroll
        for (int kw = 0; kw < 5; kw++) {
            int iw = ow - 2 + kw;
            if (iw < 0 || iw >= WW) continue;
            acc += xp[ih * WW + iw] * wp[kh * 5 + kw];
        }
    }
    float l = acc;
    float lf = l * (1.f / (1.f + __expf(-l)));
    float g = gf[idx];
    float gated = lf * (1.f / (1.f + __expf(-g)));
    out[idx] = gated * g;
}

// ---------------- host ----------------
static inline int cdiv(int a, int b) { return (a + b - 1) / b; }

extern "C" void kernel_launch(void* const* d_in, const int* in_sizes, int n_in,
                              void* d_out, int out_size)
{
    const float* x     = (const float*)d_in[0];
    const float* q_w   = (const float*)d_in[1];
    const float* q_b   = (const float*)d_in[2];
    const float* kv_w  = (const float*)d_in[3];
    const float* kv_b  = (const float*)d_in[4];
    const float* p0_w  = (const float*)d_in[5];
    const float* p0_b  = (const float*)d_in[6];
    const float* bn0_g = (const float*)d_in[7];
    const float* bn0_b = (const float*)d_in[8];
    const float* bn0_m = (const float*)d_in[9];
    const float* bn0_v = (const float*)d_in[10];
    const float* pl0_w = (const float*)d_in[11];
    const float* pl0_b = (const float*)d_in[12];
    const float* p1_w  = (const float*)d_in[13];
    const float* p1_b  = (const float*)d_in[14];
    const float* bn1_g = (const float*)d_in[15];
    const float* bn1_b = (const float*)d_in[16];
    const float* bn1_m = (const float*)d_in[17];
    const float* bn1_v = (const float*)d_in[18];
    const float* loc_w = (const float*)d_in[19];
    const float* loc_b = (const float*)d_in[20];
    const float* mix_w = (const float*)d_in[21];
    const float* mix_b = (const float*)d_in[22];
    float* out = (float*)d_out;

    float *q, *p28a, *p28b, *p14, *kv, *gf, *mixin;
    cudaGetSymbolAddress((void**)&q,     g_q);
    cudaGetSymbolAddress((void**)&p28a,  g_p28a);
    cudaGetSymbolAddress((void**)&p28b,  g_p28b);
    cudaGetSymbolAddress((void**)&p14,   g_p14);
    cudaGetSymbolAddress((void**)&kv,    g_kv);
    cudaGetSymbolAddress((void**)&gf,    g_gf);
    cudaGetSymbolAddress((void**)&mixin, g_mixin);

    cudaFuncSetAttribute(attn_k, cudaFuncAttributeMaxDynamicSharedMemorySize, (int)ATTN_SMEM_BYTES);

    dim3 tb(256);

    // 1) q_local = 1x1 conv
    conv1x1_k<<<dim3(cdiv(HW, GN), DIMC / GM, BATCH), tb>>>(q_w, x, q_b, q, DIMC, HW, DIMC);

    // 2) p0 dwconv s2 + BN0 (56->28)
    dwconv_bn_k<<<cdiv(BATCH * DIMC * S28, 256), tb>>>(
        x, p0_w, p0_b, bn0_g, bn0_b, bn0_m, bn0_v, p28a, HH, WW, H28, H28, 2, 1);

    // 3) pl0 1x1 conv (28x28)
    conv1x1_k<<<dim3(cdiv(S28, GN), DIMC / GM, BATCH), tb>>>(pl0_w, p28a, pl0_b, p28b, DIMC, S28, DIMC);

    // 4) p1 dwconv s2 + BN1 (28->14)
    dwconv_bn_k<<<cdiv(BATCH * DIMC * SP, 256), tb>>>(
        p28b, p1_w, p1_b, bn1_g, bn1_b, bn1_m, bn1_v, p14, H28, H28, HP, HP, 2, 1);

    // 5) kv 1x1 conv
    conv1x1_k<<<dim3(cdiv(SP, GN), 2 * DIMC / GM, BATCH), tb>>>(kv_w, p14, kv_b, kv, 2 * DIMC, SP, DIMC);

    // 6) fused attention: QK^T -> softmax -> PV, per (b,h)
    attn_k<<<dim3(cdiv(HW, QT), BATCH * HEADS), tb, ATTN_SMEM_BYTES>>>(q, kv, gf);

    // 7) local mixer + gating
    gate_k<<<cdiv(BATCH * DIMC * HW, 256), tb>>>(q, gf, loc_w, loc_b, mixin);

    // 8) mix 1x1 conv -> out
    conv1x1_k<<<dim3(cdiv(HW, GN), DIMC / GM, BATCH), tb>>>(mix_w, mixin, mix_b, out, DIMC, HW, DIMC);
}